// round 15
// baseline (speedup 1.0000x reference)
#include <cuda_runtime.h>
#include <cuda_bf16.h>
#include <cuda_fp16.h>
#include <cstdint>

// ---------------------------------------------------------------------------
// bs=2, seq=2048, embed=1024, heads=16, head_dim=64
// R14: R13 math (single-term fp16 everywhere, fp32 accum) with projection
// GEMMs restructured to a 3-stage cp.async pipeline with ONE sync per
// 32-K chunk (stage 16KB, 48KB/CTA, 3 CTAs/SM -> 12 warps/SM kept).
// ---------------------------------------------------------------------------

#define SEQ   2048
#define EMB   1024
#define NH    16
#define HD    64
#define ROWS  4096

__device__ __half  g_x16 [(size_t)ROWS * EMB];
__device__ __half  g_wq16[(size_t)3 * EMB * EMB];
__device__ __half  g_wo16[(size_t)EMB * EMB];
__device__ __half  g_qkv [(size_t)ROWS * 3 * EMB];
__device__ __half  g_att [(size_t)ROWS * EMB];

// ---------------------------------------------------------------------------
__device__ __forceinline__ uint32_t smem_u32(const void* p) {
    uint32_t a;
    asm("{ .reg .u64 t; cvta.to.shared.u64 t, %1; cvt.u32.u64 %0, t; }"
        : "=r"(a) : "l"(p));
    return a;
}
__device__ __forceinline__ void cp_async16(uint32_t dst, const void* src) {
    asm volatile("cp.async.cg.shared.global [%0], [%1], 16;" :: "r"(dst), "l"(src));
}
__device__ __forceinline__ void cp_commit() { asm volatile("cp.async.commit_group;"); }
template<int N>
__device__ __forceinline__ void cp_wait() {
    asm volatile("cp.async.wait_group %0;" :: "n"(N));
}
__device__ __forceinline__ void ldsm_x4(uint32_t* r, uint32_t addr) {
    asm volatile("ldmatrix.sync.aligned.m8n8.x4.shared.b16 {%0,%1,%2,%3}, [%4];"
                 : "=r"(r[0]), "=r"(r[1]), "=r"(r[2]), "=r"(r[3]) : "r"(addr));
}
__device__ __forceinline__ void ldsm_x4t(uint32_t* r, uint32_t addr) {
    asm volatile("ldmatrix.sync.aligned.m8n8.x4.trans.shared.b16 {%0,%1,%2,%3}, [%4];"
                 : "=r"(r[0]), "=r"(r[1]), "=r"(r[2]), "=r"(r[3]) : "r"(addr));
}
__device__ __forceinline__ void mma_f16(float* d, const uint32_t* a, const uint32_t* b) {
    asm volatile(
        "mma.sync.aligned.m16n8k16.row.col.f32.f16.f16.f32 "
        "{%0,%1,%2,%3}, {%4,%5,%6,%7}, {%8,%9}, {%0,%1,%2,%3};"
        : "+f"(d[0]), "+f"(d[1]), "+f"(d[2]), "+f"(d[3])
        : "r"(a[0]), "r"(a[1]), "r"(a[2]), "r"(a[3]), "r"(b[0]), "r"(b[1]));
}
__device__ __forceinline__ uint32_t pack_h2(float x, float y) {
    __half2 h = __floats2half2_rn(x, y);
    return *(uint32_t*)&h;
}

// ---------------------------------------------------------------------------
// Fused fp32 -> fp16 conversion for x, w_qkv, w_out (single launch).
// ---------------------------------------------------------------------------
#define XN   ((size_t)ROWS * EMB)
#define WQN  ((size_t)3 * EMB * EMB)
#define WON  ((size_t)EMB * EMB)
#define CVT_TOT (XN + WQN + WON)

__global__ __launch_bounds__(256)
void cvt_all(const float* __restrict__ x, const float* __restrict__ wq,
             const float* __restrict__ wo,
             __half* __restrict__ x16, __half* __restrict__ wq16,
             __half* __restrict__ wo16)
{
    size_t i = ((size_t)blockIdx.x * 256 + threadIdx.x) * 4;
    const float* in; __half* o; size_t off;
    if (i < XN)            { in = x;  o = x16;  off = i; }
    else if (i < XN + WQN) { in = wq; o = wq16; off = i - XN; }
    else                   { in = wo; o = wo16; off = i - XN - WQN; }
    float4 v = *(const float4*)(in + off);
    *(__half2*)(o + off)     = __floats2half2_rn(v.x, v.y);
    *(__half2*)(o + off + 2) = __floats2half2_rn(v.z, v.w);
}

// ---------------------------------------------------------------------------
// fp16 GEMM: C = A B^T. Output 0: fp32+bias, 2: fp16.
// CTA 128x128, 128 threads = 4 warps of 64x64.
// 3-stage cp.async pipeline, ONE __syncthreads per 32-K chunk.
// Stage = 16KB: 128 rows x 128B; A-row r logical chunks 0-3 at slot
// (c ^ (r&7))*16, B-row r logical chunks 4-7 at ((c+4) ^ (r&7))*16.
// ---------------------------------------------------------------------------
#define STG_B   16384
#define GSMEM   (3 * STG_B)              // 49152 -> 3 CTAs/SM

template<int OUTM>
__global__ __launch_bounds__(128, 3)
void gemm_f16(const __half* __restrict__ A, const __half* __restrict__ B,
              const float* __restrict__ bias, float* __restrict__ C,
              __half* __restrict__ C16,
              int M, int N, int K)
{
    extern __shared__ char smem[];
    const uint32_t sbase = smem_u32(smem);

    const int t    = threadIdx.x;
    const int warp = t >> 5;
    const int lane = t & 31;
    const int wm   = warp >> 1;
    const int wn   = warp & 1;
    const int bm   = blockIdx.y * 128;
    const int bn   = blockIdx.x * 128;

    const int aRow = (lane & 15);
    const int aKh  = lane >> 4;
    const int bN   = ((lane >> 4) << 3) + (lane & 7);
    const int bKh  = (lane >> 3) & 1;

    float acc[4][8][4];
    #pragma unroll
    for (int i = 0; i < 4; i++)
        #pragma unroll
        for (int j = 0; j < 8; j++)
            #pragma unroll
            for (int r = 0; r < 4; r++) acc[i][j][r] = 0.f;

    const int nck = K >> 5;

    // loader: 128 threads x 8 x 16B = 16KB. lchunk 0-3: A, 4-7: B.
    const int lchunk = t & 7;
    const int lrow   = t >> 3;
    auto load_chunk = [&](int ck, int stg) {
        const int ke = (ck << 5) + (lchunk & 3) * 8;
        const __half* base = (lchunk < 4)
            ? A + (size_t)bm * K + ke
            : B + (size_t)bn * K + ke;
        #pragma unroll
        for (int it = 0; it < 8; it++) {
            const int row = it * 16 + lrow;
            uint32_t dst = sbase + stg * STG_B
                         + row * 128 + ((lchunk ^ (row & 7)) << 4);
            cp_async16(dst, base + (size_t)row * K);
        }
    };

    load_chunk(0, 0); cp_commit();
    load_chunk(1, 1); cp_commit();

    int stg = 0;
    for (int ck = 0; ck < nck; ck++) {
        if (ck + 1 < nck) cp_wait<1>(); else cp_wait<0>();
        __syncthreads();   // stage ck ready; also proves all warps done with ck-1
        if (ck + 2 < nck) {
            int ns = stg + 2; if (ns >= 3) ns -= 3;   // == (ck-1)%3: safe to overwrite
            load_chunk(ck + 2, ns); cp_commit();
        }

        const uint32_t stgb = sbase + stg * STG_B;
        #pragma unroll
        for (int ks = 0; ks < 2; ks++) {
            uint32_t af[4][4], bf[8][2];
            #pragma unroll
            for (int mi = 0; mi < 4; mi++) {
                const int row = wm * 64 + mi * 16 + aRow;
                const int ch  = ks * 2 + aKh;
                ldsm_x4(af[mi], stgb + row * 128 + ((ch ^ (row & 7)) << 4));
            }
            #pragma unroll
            for (int p = 0; p < 4; p++) {
                const int row = wn * 64 + p * 16 + bN;
                const int ch  = ks * 2 + bKh + 4;
                uint32_t rb4[4];
                ldsm_x4(rb4, stgb + row * 128 + ((ch ^ (row & 7)) << 4));
                bf[p * 2][0] = rb4[0]; bf[p * 2][1] = rb4[1];
                bf[p * 2 + 1][0] = rb4[2]; bf[p * 2 + 1][1] = rb4[3];
            }
            #pragma unroll
            for (int mi = 0; mi < 4; mi++)
                #pragma unroll
                for (int nj = 0; nj < 8; nj++)
                    mma_f16(acc[mi][nj], af[mi], bf[nj]);
        }
        if (++stg == 3) stg = 0;
    }

    const int r0 = bm + wm * 64 + (lane >> 2);
    const int c0 = bn + wn * 64 + (lane & 3) * 2;
    #pragma unroll
    for (int mi = 0; mi < 4; mi++)
        #pragma unroll
        for (int nj = 0; nj < 8; nj++) {
            int row = r0 + mi * 16;
            int col = c0 + nj * 8;
            float2 v0 = make_float2(acc[mi][nj][0], acc[mi][nj][1]);
            float2 v1 = make_float2(acc[mi][nj][2], acc[mi][nj][3]);
            if (OUTM == 0) {
                v0.x += bias[col]; v0.y += bias[col + 1];
                v1.x += bias[col]; v1.y += bias[col + 1];
                *(float2*)(C + (size_t)row * N + col)       = v0;
                *(float2*)(C + (size_t)(row + 8) * N + col) = v1;
            } else {
                *(__half2*)(C16 + (size_t)row * N + col)       = __floats2half2_rn(v0.x, v0.y);
                *(__half2*)(C16 + (size_t)(row + 8) * N + col) = __floats2half2_rn(v1.x, v1.y);
            }
        }
}

// ---------------------------------------------------------------------------
// Flash attention, single-term fp16 mma. 3-stage KV pipeline (K,V per stage).
// qkv fp16 [4096][3072]; head h: q at h*192, k +64, v +128. Output fp16.
// (unchanged from R13 — passes)
// ---------------------------------------------------------------------------
#define ATS    72
#define QTILE  (128 * ATS * 2)
#define KVT    (64 * ATS * 2)
#define KVSTG  (2 * KVT)
#define ASMEM  (3 * KVSTG)

__global__ __launch_bounds__(256)
void attn_mma(const __half* __restrict__ qkv, __half* __restrict__ o16)
{
    extern __shared__ char smem[];
    const uint32_t sbase = smem_u32(smem);

    const int t    = threadIdx.x;
    const int warp = t >> 5;
    const int lane = t & 31;
    const int qb   = 15 - blockIdx.x;
    const int h    = blockIdx.y;
    const int b    = blockIdx.z;
    const int wr0  = warp * 16;

    const int aRow = lane & 15;
    const int aKh  = lane >> 4;
    const int bN   = ((lane >> 4) << 3) + (lane & 7);
    const int bKh  = (lane >> 3) & 1;
    const int vRow = ((lane >> 3) & 1) * 8 + (lane & 7);
    const int vCol = (lane >> 4) * 8;

    const size_t qrow0 = (size_t)b * SEQ + qb * 128;

    #pragma unroll
    for (int it = 0; it < 4; it++) {
        const int linear = it * 256 + t;
        const int row = linear >> 3;
        const int kc  = (linear & 7) << 3;
        cp_async16(sbase + (row * ATS + kc) * 2,
                   qkv + (qrow0 + row) * 3072 + h * 192 + kc);
    }
    cp_commit();
    cp_wait<0>();
    __syncthreads();

    uint32_t qf[4][4];
    #pragma unroll
    for (int kt = 0; kt < 4; kt++)
        ldsm_x4(qf[kt], sbase + ((wr0 + aRow) * ATS + kt * 16 + aKh * 8) * 2);
    __syncthreads();

    float oacc[8][4];
    #pragma unroll
    for (int i = 0; i < 8; i++)
        #pragma unroll
        for (int j = 0; j < 4; j++) oacc[i][j] = 0.f;
    float m0 = -1e30f, m1 = -1e30f, l0 = 0.f, l1 = 0.f;

    const int r0g = qb * 128 + wr0 + (lane >> 2);
    const int r1g = r0g + 8;
    const int nblk = (qb + 1) * 2;

    auto load_kv = [&](int blk, int s) {
        const int j0 = blk * 64;
        const uint32_t kb = sbase + s * KVSTG;
        #pragma unroll
        for (int it = 0; it < 2; it++) {
            const int linear = it * 256 + t;
            const int row = linear >> 3;
            const int kc  = (linear & 7) << 3;
            uint32_t d = kb + (row * ATS + kc) * 2;
            const size_t gk = ((size_t)b * SEQ + j0 + row) * 3072 + h * 192 + 64 + kc;
            cp_async16(d,       qkv + gk);
            cp_async16(d + KVT, qkv + gk + 64);
        }
    };

    load_kv(0, 0); cp_commit();
    if (nblk > 1) { load_kv(1, 1); cp_commit(); }

    int stg = 0;
    for (int blk = 0; blk < nblk; blk++) {
        const int j0 = blk * 64;
        if (blk + 1 < nblk) cp_wait<1>(); else cp_wait<0>();
        __syncthreads();
        if (blk + 2 < nblk) {
            int ns = stg + 2; if (ns >= 3) ns -= 3;
            load_kv(blk + 2, ns); cp_commit();
        }

        const bool active = (j0 <= qb * 128 + wr0 + 15);
        if (active) {
            const uint32_t kb = sbase + stg * KVSTG;

            float sacc[8][4];
            #pragma unroll
            for (int i = 0; i < 8; i++)
                #pragma unroll
                for (int j = 0; j < 4; j++) sacc[i][j] = 0.f;
            #pragma unroll
            for (int kt = 0; kt < 4; kt++) {
                #pragma unroll
                for (int nt2 = 0; nt2 < 4; nt2++) {
                    uint32_t rk[4];
                    ldsm_x4(rk, kb + ((nt2 * 16 + bN) * ATS + kt * 16 + bKh * 8) * 2);
                    uint32_t k0[2] = {rk[0], rk[1]}, k1[2] = {rk[2], rk[3]};
                    mma_f16(sacc[nt2 * 2],     qf[kt], k0);
                    mma_f16(sacc[nt2 * 2 + 1], qf[kt], k1);
                }
            }

            if (j0 + 63 > qb * 128 + wr0) {
                #pragma unroll
                for (int nt = 0; nt < 8; nt++) {
                    const int c = j0 + nt * 8 + (lane & 3) * 2;
                    if (c     > r0g) sacc[nt][0] = -1e30f;
                    if (c + 1 > r0g) sacc[nt][1] = -1e30f;
                    if (c     > r1g) sacc[nt][2] = -1e30f;
                    if (c + 1 > r1g) sacc[nt][3] = -1e30f;
                }
            }

            float mx0 = -1e30f, mx1 = -1e30f;
            #pragma unroll
            for (int nt = 0; nt < 8; nt++) {
                mx0 = fmaxf(mx0, fmaxf(sacc[nt][0], sacc[nt][1]));
                mx1 = fmaxf(mx1, fmaxf(sacc[nt][2], sacc[nt][3]));
            }
            mx0 = fmaxf(mx0, __shfl_xor_sync(0xffffffffu, mx0, 1));
            mx0 = fmaxf(mx0, __shfl_xor_sync(0xffffffffu, mx0, 2));
            mx1 = fmaxf(mx1, __shfl_xor_sync(0xffffffffu, mx1, 1));
            mx1 = fmaxf(mx1, __shfl_xor_sync(0xffffffffu, mx1, 2));
            mx0 *= 0.125f; mx1 *= 0.125f;
            const float nm0 = fmaxf(m0, mx0), nm1 = fmaxf(m1, mx1);
            const float rs0 = __expf(m0 - nm0), rs1 = __expf(m1 - nm1);
            m0 = nm0; m1 = nm1;

            float sum0 = 0.f, sum1 = 0.f;
            #pragma unroll
            for (int nt = 0; nt < 8; nt++) {
                float p0 = __expf(fmaf(sacc[nt][0], 0.125f, -nm0));
                float p1 = __expf(fmaf(sacc[nt][1], 0.125f, -nm0));
                float p2 = __expf(fmaf(sacc[nt][2], 0.125f, -nm1));
                float p3 = __expf(fmaf(sacc[nt][3], 0.125f, -nm1));
                sacc[nt][0] = p0; sacc[nt][1] = p1;
                sacc[nt][2] = p2; sacc[nt][3] = p3;
                sum0 += p0 + p1; sum1 += p2 + p3;
            }
            sum0 += __shfl_xor_sync(0xffffffffu, sum0, 1);
            sum0 += __shfl_xor_sync(0xffffffffu, sum0, 2);
            sum1 += __shfl_xor_sync(0xffffffffu, sum1, 1);
            sum1 += __shfl_xor_sync(0xffffffffu, sum1, 2);
            l0 = l0 * rs0 + sum0;
            l1 = l1 * rs1 + sum1;

            #pragma unroll
            for (int dt = 0; dt < 8; dt++) {
                oacc[dt][0] *= rs0; oacc[dt][1] *= rs0;
                oacc[dt][2] *= rs1; oacc[dt][3] *= rs1;
            }

            #pragma unroll
            for (int kt = 0; kt < 4; kt++) {
                uint32_t vf[8][2];
                #pragma unroll
                for (int dt2 = 0; dt2 < 4; dt2++) {
                    uint32_t rv[4];
                    ldsm_x4t(rv, kb + KVT + ((kt * 16 + vRow) * ATS + dt2 * 16 + vCol) * 2);
                    vf[dt2 * 2][0] = rv[0]; vf[dt2 * 2][1] = rv[1];
                    vf[dt2 * 2 + 1][0] = rv[2]; vf[dt2 * 2 + 1][1] = rv[3];
                }
                uint32_t Pa[4];
                #pragma unroll
                for (int half_ = 0; half_ < 2; half_++) {
                    const float* s = sacc[kt * 2 + half_];
                    Pa[half_ * 2]     = pack_h2(s[0], s[1]);
                    Pa[half_ * 2 + 1] = pack_h2(s[2], s[3]);
                }
                #pragma unroll
                for (int dt = 0; dt < 8; dt++)
                    mma_f16(oacc[dt], Pa, vf[dt]);
            }
        }
        if (++stg == 3) stg = 0;
    }

    const float inv0 = 1.f / l0, inv1 = 1.f / l1;
    const size_t ro0 = (size_t)b * SEQ + qb * 128 + wr0 + (lane >> 2);
    const size_t ro1 = ro0 + 8;
    #pragma unroll
    for (int dt = 0; dt < 8; dt++) {
        const int col = h * 64 + dt * 8 + (lane & 3) * 2;
        *(__half2*)(o16 + ro0 * EMB + col) =
            __floats2half2_rn(oacc[dt][0] * inv0, oacc[dt][1] * inv0);
        *(__half2*)(o16 + ro1 * EMB + col) =
            __floats2half2_rn(oacc[dt][2] * inv1, oacc[dt][3] * inv1);
    }
}

// ---------------------------------------------------------------------------
extern "C" void kernel_launch(void* const* d_in, const int* in_sizes, int n_in,
                              void* d_out, int out_size)
{
    const float* x    = (const float*)d_in[0];
    const float* wqkv = (const float*)d_in[1];
    const float* wout = (const float*)d_in[2];
    const float* bout = (const float*)d_in[3];
    float* out = (float*)d_out;

    __half *x16, *wq16, *wo16, *qkv16, *att16;
    cudaGetSymbolAddress((void**)&x16,   g_x16);
    cudaGetSymbolAddress((void**)&wq16,  g_wq16);
    cudaGetSymbolAddress((void**)&wo16,  g_wo16);
    cudaGetSymbolAddress((void**)&qkv16, g_qkv);
    cudaGetSymbolAddress((void**)&att16, g_att);

    cudaFuncSetAttribute(gemm_f16<2>,
                         cudaFuncAttributeMaxDynamicSharedMemorySize, GSMEM);
    cudaFuncSetAttribute(gemm_f16<0>,
                         cudaFuncAttributeMaxDynamicSharedMemorySize, GSMEM);
    cudaFuncSetAttribute(attn_mma,
                         cudaFuncAttributeMaxDynamicSharedMemorySize, ASMEM);

    // 0) fp16 conversions (one launch)
    cvt_all<<<CVT_TOT / 1024, 256>>>(x, wqkv, wout, x16, wq16, wo16);

    // 1) QKV projection (fp16) -> fp16 q,k,v
    gemm_f16<2><<<dim3(3072 / 128, ROWS / 128), 128, GSMEM>>>(
        x16, wq16, nullptr, nullptr, qkv16, ROWS, 3072, EMB);

    // 2) causal flash attention (fp16) -> fp16
    attn_mma<<<dim3(SEQ / 128, NH, 2), 256, ASMEM>>>(qkv16, att16);

    // 3) out projection + bias (fp16) -> fp32
    gemm_f16<0><<<dim3(EMB / 128, ROWS / 128), 128, GSMEM>>>(
        att16, wo16, bout, out, nullptr, ROWS, EMB, EMB);
}

// round 16
// speedup vs baseline: 1.0937x; 1.0937x over previous
#include <cuda_runtime.h>
#include <cuda_bf16.h>
#include <cuda_fp16.h>
#include <cstdint>

// ---------------------------------------------------------------------------
// bs=2, seq=2048, embed=1024, heads=16, head_dim=64
// R16: R13 GEMMs (2-stage, best measured) + paired-q-tile attention:
// each CTA handles q-tiles {15-bx, bx} -> uniform 34 KV-blocks/CTA,
// 256 CTAs = one balanced wave (was 512 ragged CTAs over 1.7 waves).
// ---------------------------------------------------------------------------

#define SEQ   2048
#define EMB   1024
#define NH    16
#define HD    64
#define ROWS  4096

__device__ __half  g_x16 [(size_t)ROWS * EMB];
__device__ __half  g_wq16[(size_t)3 * EMB * EMB];
__device__ __half  g_wo16[(size_t)EMB * EMB];
__device__ __half  g_qkv [(size_t)ROWS * 3 * EMB];
__device__ __half  g_att [(size_t)ROWS * EMB];

// ---------------------------------------------------------------------------
__device__ __forceinline__ uint32_t smem_u32(const void* p) {
    uint32_t a;
    asm("{ .reg .u64 t; cvta.to.shared.u64 t, %1; cvt.u32.u64 %0, t; }"
        : "=r"(a) : "l"(p));
    return a;
}
__device__ __forceinline__ void cp_async16(uint32_t dst, const void* src) {
    asm volatile("cp.async.cg.shared.global [%0], [%1], 16;" :: "r"(dst), "l"(src));
}
__device__ __forceinline__ void cp_commit() { asm volatile("cp.async.commit_group;"); }
template<int N>
__device__ __forceinline__ void cp_wait() {
    asm volatile("cp.async.wait_group %0;" :: "n"(N));
}
__device__ __forceinline__ void ldsm_x4(uint32_t* r, uint32_t addr) {
    asm volatile("ldmatrix.sync.aligned.m8n8.x4.shared.b16 {%0,%1,%2,%3}, [%4];"
                 : "=r"(r[0]), "=r"(r[1]), "=r"(r[2]), "=r"(r[3]) : "r"(addr));
}
__device__ __forceinline__ void ldsm_x4t(uint32_t* r, uint32_t addr) {
    asm volatile("ldmatrix.sync.aligned.m8n8.x4.trans.shared.b16 {%0,%1,%2,%3}, [%4];"
                 : "=r"(r[0]), "=r"(r[1]), "=r"(r[2]), "=r"(r[3]) : "r"(addr));
}
__device__ __forceinline__ void mma_f16(float* d, const uint32_t* a, const uint32_t* b) {
    asm volatile(
        "mma.sync.aligned.m16n8k16.row.col.f32.f16.f16.f32 "
        "{%0,%1,%2,%3}, {%4,%5,%6,%7}, {%8,%9}, {%0,%1,%2,%3};"
        : "+f"(d[0]), "+f"(d[1]), "+f"(d[2]), "+f"(d[3])
        : "r"(a[0]), "r"(a[1]), "r"(a[2]), "r"(a[3]), "r"(b[0]), "r"(b[1]));
}
__device__ __forceinline__ uint32_t pack_h2(float x, float y) {
    __half2 h = __floats2half2_rn(x, y);
    return *(uint32_t*)&h;
}

// ---------------------------------------------------------------------------
// Fused fp32 -> fp16 conversion for x, w_qkv, w_out (single launch).
// ---------------------------------------------------------------------------
#define XN   ((size_t)ROWS * EMB)
#define WQN  ((size_t)3 * EMB * EMB)
#define WON  ((size_t)EMB * EMB)
#define CVT_TOT (XN + WQN + WON)

__global__ __launch_bounds__(256)
void cvt_all(const float* __restrict__ x, const float* __restrict__ wq,
             const float* __restrict__ wo,
             __half* __restrict__ x16, __half* __restrict__ wq16,
             __half* __restrict__ wo16)
{
    size_t i = ((size_t)blockIdx.x * 256 + threadIdx.x) * 4;
    const float* in; __half* o; size_t off;
    if (i < XN)            { in = x;  o = x16;  off = i; }
    else if (i < XN + WQN) { in = wq; o = wq16; off = i - XN; }
    else                   { in = wo; o = wo16; off = i - XN - WQN; }
    float4 v = *(const float4*)(in + off);
    *(__half2*)(o + off)     = __floats2half2_rn(v.x, v.y);
    *(__half2*)(o + off + 2) = __floats2half2_rn(v.z, v.w);
}

// ---------------------------------------------------------------------------
// fp16 GEMM (R13 form): C = A B^T. Output 0: fp32+bias, 2: fp16.
// CTA 128x128, 128 threads = 4 warps of 64x64, 2-stage cp.async.
// Stage = 16KB: 128 rows x 128B; A logical chunks 0-3 at (c^(r&7))*16,
// B logical chunks 4-7 at ((c+4)^(r&7))*16.
// ---------------------------------------------------------------------------
#define STG_B   16384
#define GSMEM   (2 * STG_B)              // 32768

template<int OUTM>
__global__ __launch_bounds__(128, 3)
void gemm_f16(const __half* __restrict__ A, const __half* __restrict__ B,
              const float* __restrict__ bias, float* __restrict__ C,
              __half* __restrict__ C16,
              int M, int N, int K)
{
    extern __shared__ char smem[];
    const uint32_t sbase = smem_u32(smem);

    const int t    = threadIdx.x;
    const int warp = t >> 5;
    const int lane = t & 31;
    const int wm   = warp >> 1;
    const int wn   = warp & 1;
    const int bm   = blockIdx.y * 128;
    const int bn   = blockIdx.x * 128;

    const int aRow = (lane & 15);
    const int aKh  = lane >> 4;
    const int bN   = ((lane >> 4) << 3) + (lane & 7);
    const int bKh  = (lane >> 3) & 1;

    float acc[4][8][4];
    #pragma unroll
    for (int i = 0; i < 4; i++)
        #pragma unroll
        for (int j = 0; j < 8; j++)
            #pragma unroll
            for (int r = 0; r < 4; r++) acc[i][j][r] = 0.f;

    const int nck = K >> 5;

    const int lchunk = t & 7;
    const int lrow   = t >> 3;
    auto load_chunk = [&](int ck, int stg) {
        const int ke = (ck << 5) + (lchunk & 3) * 8;
        const __half* base = (lchunk < 4)
            ? A + (size_t)bm * K + ke
            : B + (size_t)bn * K + ke;
        #pragma unroll
        for (int it = 0; it < 8; it++) {
            const int row = it * 16 + lrow;
            uint32_t dst = sbase + stg * STG_B
                         + row * 128 + ((lchunk ^ (row & 7)) << 4);
            cp_async16(dst, base + (size_t)row * K);
        }
    };

    load_chunk(0, 0); cp_commit();

    for (int ck = 0; ck < nck; ck++) {
        if (ck + 1 < nck) {
            load_chunk(ck + 1, (ck + 1) & 1); cp_commit(); cp_wait<1>();
        } else {
            cp_wait<0>();
        }
        __syncthreads();

        const uint32_t stgb = sbase + (ck & 1) * STG_B;
        #pragma unroll
        for (int ks = 0; ks < 2; ks++) {
            uint32_t af[4][4], bf[8][2];
            #pragma unroll
            for (int mi = 0; mi < 4; mi++) {
                const int row = wm * 64 + mi * 16 + aRow;
                const int ch  = ks * 2 + aKh;
                ldsm_x4(af[mi], stgb + row * 128 + ((ch ^ (row & 7)) << 4));
            }
            #pragma unroll
            for (int p = 0; p < 4; p++) {
                const int row = wn * 64 + p * 16 + bN;
                const int ch  = ks * 2 + bKh + 4;
                uint32_t rb4[4];
                ldsm_x4(rb4, stgb + row * 128 + ((ch ^ (row & 7)) << 4));
                bf[p * 2][0] = rb4[0]; bf[p * 2][1] = rb4[1];
                bf[p * 2 + 1][0] = rb4[2]; bf[p * 2 + 1][1] = rb4[3];
            }
            #pragma unroll
            for (int mi = 0; mi < 4; mi++)
                #pragma unroll
                for (int nj = 0; nj < 8; nj++)
                    mma_f16(acc[mi][nj], af[mi], bf[nj]);
        }
        __syncthreads();
    }

    const int r0 = bm + wm * 64 + (lane >> 2);
    const int c0 = bn + wn * 64 + (lane & 3) * 2;
    #pragma unroll
    for (int mi = 0; mi < 4; mi++)
        #pragma unroll
        for (int nj = 0; nj < 8; nj++) {
            int row = r0 + mi * 16;
            int col = c0 + nj * 8;
            float2 v0 = make_float2(acc[mi][nj][0], acc[mi][nj][1]);
            float2 v1 = make_float2(acc[mi][nj][2], acc[mi][nj][3]);
            if (OUTM == 0) {
                v0.x += bias[col]; v0.y += bias[col + 1];
                v1.x += bias[col]; v1.y += bias[col + 1];
                *(float2*)(C + (size_t)row * N + col)       = v0;
                *(float2*)(C + (size_t)(row + 8) * N + col) = v1;
            } else {
                *(__half2*)(C16 + (size_t)row * N + col)       = __floats2half2_rn(v0.x, v0.y);
                *(__half2*)(C16 + (size_t)(row + 8) * N + col) = __floats2half2_rn(v1.x, v1.y);
            }
        }
}

// ---------------------------------------------------------------------------
// Flash attention, fp16 mma, PAIRED q-tiles: CTA bx handles qb = 15-bx then
// qb = bx -> uniform 34 KV-blocks per CTA; grid (8, 16, 2) = 256 CTAs.
// 3-stage KV pipeline per q-tile. Output fp16.
// ---------------------------------------------------------------------------
#define ATS    72
#define QTILE  (128 * ATS * 2)
#define KVT    (64 * ATS * 2)
#define KVSTG  (2 * KVT)
#define ASMEM  (3 * KVSTG)

__global__ __launch_bounds__(256)
void attn_mma(const __half* __restrict__ qkv, __half* __restrict__ o16)
{
    extern __shared__ char smem[];
    const uint32_t sbase = smem_u32(smem);

    const int t    = threadIdx.x;
    const int warp = t >> 5;
    const int lane = t & 31;
    const int bx   = blockIdx.x;          // 0..7
    const int h    = blockIdx.y;
    const int b    = blockIdx.z;
    const int wr0  = warp * 16;

    const int aRow = lane & 15;
    const int aKh  = lane >> 4;
    const int bN   = ((lane >> 4) << 3) + (lane & 7);
    const int bKh  = (lane >> 3) & 1;
    const int vRow = ((lane >> 3) & 1) * 8 + (lane & 7);
    const int vCol = (lane >> 4) * 8;

    for (int half_idx = 0; half_idx < 2; half_idx++) {
        const int qb = half_idx == 0 ? (15 - bx) : bx;
        const size_t qrow0 = (size_t)b * SEQ + qb * 128;

        // ---- stage Q, build A-fragments, release smem
        #pragma unroll
        for (int it = 0; it < 4; it++) {
            const int linear = it * 256 + t;
            const int row = linear >> 3;
            const int kc  = (linear & 7) << 3;
            cp_async16(sbase + (row * ATS + kc) * 2,
                       qkv + (qrow0 + row) * 3072 + h * 192 + kc);
        }
        cp_commit();
        cp_wait<0>();
        __syncthreads();

        uint32_t qf[4][4];
        #pragma unroll
        for (int kt = 0; kt < 4; kt++)
            ldsm_x4(qf[kt], sbase + ((wr0 + aRow) * ATS + kt * 16 + aKh * 8) * 2);
        __syncthreads();

        float oacc[8][4];
        #pragma unroll
        for (int i = 0; i < 8; i++)
            #pragma unroll
            for (int j = 0; j < 4; j++) oacc[i][j] = 0.f;
        float m0 = -1e30f, m1 = -1e30f, l0 = 0.f, l1 = 0.f;

        const int r0g = qb * 128 + wr0 + (lane >> 2);
        const int r1g = r0g + 8;
        const int nblk = (qb + 1) * 2;

        auto load_kv = [&](int blk, int s) {
            const int j0 = blk * 64;
            const uint32_t kb = sbase + s * KVSTG;
            #pragma unroll
            for (int it = 0; it < 2; it++) {
                const int linear = it * 256 + t;
                const int row = linear >> 3;
                const int kc  = (linear & 7) << 3;
                uint32_t d = kb + (row * ATS + kc) * 2;
                const size_t gk = ((size_t)b * SEQ + j0 + row) * 3072 + h * 192 + 64 + kc;
                cp_async16(d,       qkv + gk);
                cp_async16(d + KVT, qkv + gk + 64);
            }
        };

        load_kv(0, 0); cp_commit();
        if (nblk > 1) { load_kv(1, 1); cp_commit(); }

        int stg = 0;
        for (int blk = 0; blk < nblk; blk++) {
            const int j0 = blk * 64;
            if (blk + 1 < nblk) cp_wait<1>(); else cp_wait<0>();
            __syncthreads();
            if (blk + 2 < nblk) {
                int ns = stg + 2; if (ns >= 3) ns -= 3;
                load_kv(blk + 2, ns); cp_commit();
            }

            const bool active = (j0 <= qb * 128 + wr0 + 15);
            if (active) {
                const uint32_t kb = sbase + stg * KVSTG;

                float sacc[8][4];
                #pragma unroll
                for (int i = 0; i < 8; i++)
                    #pragma unroll
                    for (int j = 0; j < 4; j++) sacc[i][j] = 0.f;
                #pragma unroll
                for (int kt = 0; kt < 4; kt++) {
                    #pragma unroll
                    for (int nt2 = 0; nt2 < 4; nt2++) {
                        uint32_t rk[4];
                        ldsm_x4(rk, kb + ((nt2 * 16 + bN) * ATS + kt * 16 + bKh * 8) * 2);
                        uint32_t k0[2] = {rk[0], rk[1]}, k1[2] = {rk[2], rk[3]};
                        mma_f16(sacc[nt2 * 2],     qf[kt], k0);
                        mma_f16(sacc[nt2 * 2 + 1], qf[kt], k1);
                    }
                }

                if (j0 + 63 > qb * 128 + wr0) {
                    #pragma unroll
                    for (int nt = 0; nt < 8; nt++) {
                        const int c = j0 + nt * 8 + (lane & 3) * 2;
                        if (c     > r0g) sacc[nt][0] = -1e30f;
                        if (c + 1 > r0g) sacc[nt][1] = -1e30f;
                        if (c     > r1g) sacc[nt][2] = -1e30f;
                        if (c + 1 > r1g) sacc[nt][3] = -1e30f;
                    }
                }

                float mx0 = -1e30f, mx1 = -1e30f;
                #pragma unroll
                for (int nt = 0; nt < 8; nt++) {
                    mx0 = fmaxf(mx0, fmaxf(sacc[nt][0], sacc[nt][1]));
                    mx1 = fmaxf(mx1, fmaxf(sacc[nt][2], sacc[nt][3]));
                }
                mx0 = fmaxf(mx0, __shfl_xor_sync(0xffffffffu, mx0, 1));
                mx0 = fmaxf(mx0, __shfl_xor_sync(0xffffffffu, mx0, 2));
                mx1 = fmaxf(mx1, __shfl_xor_sync(0xffffffffu, mx1, 1));
                mx1 = fmaxf(mx1, __shfl_xor_sync(0xffffffffu, mx1, 2));
                mx0 *= 0.125f; mx1 *= 0.125f;
                const float nm0 = fmaxf(m0, mx0), nm1 = fmaxf(m1, mx1);
                const float rs0 = __expf(m0 - nm0), rs1 = __expf(m1 - nm1);
                m0 = nm0; m1 = nm1;

                float sum0 = 0.f, sum1 = 0.f;
                #pragma unroll
                for (int nt = 0; nt < 8; nt++) {
                    float p0 = __expf(fmaf(sacc[nt][0], 0.125f, -nm0));
                    float p1 = __expf(fmaf(sacc[nt][1], 0.125f, -nm0));
                    float p2 = __expf(fmaf(sacc[nt][2], 0.125f, -nm1));
                    float p3 = __expf(fmaf(sacc[nt][3], 0.125f, -nm1));
                    sacc[nt][0] = p0; sacc[nt][1] = p1;
                    sacc[nt][2] = p2; sacc[nt][3] = p3;
                    sum0 += p0 + p1; sum1 += p2 + p3;
                }
                sum0 += __shfl_xor_sync(0xffffffffu, sum0, 1);
                sum0 += __shfl_xor_sync(0xffffffffu, sum0, 2);
                sum1 += __shfl_xor_sync(0xffffffffu, sum1, 1);
                sum1 += __shfl_xor_sync(0xffffffffu, sum1, 2);
                l0 = l0 * rs0 + sum0;
                l1 = l1 * rs1 + sum1;

                #pragma unroll
                for (int dt = 0; dt < 8; dt++) {
                    oacc[dt][0] *= rs0; oacc[dt][1] *= rs0;
                    oacc[dt][2] *= rs1; oacc[dt][3] *= rs1;
                }

                #pragma unroll
                for (int kt = 0; kt < 4; kt++) {
                    uint32_t vf[8][2];
                    #pragma unroll
                    for (int dt2 = 0; dt2 < 4; dt2++) {
                        uint32_t rv[4];
                        ldsm_x4t(rv, kb + KVT + ((kt * 16 + vRow) * ATS + dt2 * 16 + vCol) * 2);
                        vf[dt2 * 2][0] = rv[0]; vf[dt2 * 2][1] = rv[1];
                        vf[dt2 * 2 + 1][0] = rv[2]; vf[dt2 * 2 + 1][1] = rv[3];
                    }
                    uint32_t Pa[4];
                    #pragma unroll
                    for (int hh = 0; hh < 2; hh++) {
                        const float* s = sacc[kt * 2 + hh];
                        Pa[hh * 2]     = pack_h2(s[0], s[1]);
                        Pa[hh * 2 + 1] = pack_h2(s[2], s[3]);
                    }
                    #pragma unroll
                    for (int dt = 0; dt < 8; dt++)
                        mma_f16(oacc[dt], Pa, vf[dt]);
                }
            }
            if (++stg == 3) stg = 0;
        }

        // ---- epilogue for this q-tile
        const float inv0 = 1.f / l0, inv1 = 1.f / l1;
        const size_t ro0 = (size_t)b * SEQ + qb * 128 + wr0 + (lane >> 2);
        const size_t ro1 = ro0 + 8;
        #pragma unroll
        for (int dt = 0; dt < 8; dt++) {
            const int col = h * 64 + dt * 8 + (lane & 3) * 2;
            *(__half2*)(o16 + ro0 * EMB + col) =
                __floats2half2_rn(oacc[dt][0] * inv0, oacc[dt][1] * inv0);
            *(__half2*)(o16 + ro1 * EMB + col) =
                __floats2half2_rn(oacc[dt][2] * inv1, oacc[dt][3] * inv1);
        }
        __syncthreads();   // all warps done with smem before next q-tile restages
    }
}

// ---------------------------------------------------------------------------
extern "C" void kernel_launch(void* const* d_in, const int* in_sizes, int n_in,
                              void* d_out, int out_size)
{
    const float* x    = (const float*)d_in[0];
    const float* wqkv = (const float*)d_in[1];
    const float* wout = (const float*)d_in[2];
    const float* bout = (const float*)d_in[3];
    float* out = (float*)d_out;

    __half *x16, *wq16, *wo16, *qkv16, *att16;
    cudaGetSymbolAddress((void**)&x16,   g_x16);
    cudaGetSymbolAddress((void**)&wq16,  g_wq16);
    cudaGetSymbolAddress((void**)&wo16,  g_wo16);
    cudaGetSymbolAddress((void**)&qkv16, g_qkv);
    cudaGetSymbolAddress((void**)&att16, g_att);

    cudaFuncSetAttribute(gemm_f16<2>,
                         cudaFuncAttributeMaxDynamicSharedMemorySize, GSMEM);
    cudaFuncSetAttribute(gemm_f16<0>,
                         cudaFuncAttributeMaxDynamicSharedMemorySize, GSMEM);
    cudaFuncSetAttribute(attn_mma,
                         cudaFuncAttributeMaxDynamicSharedMemorySize, ASMEM);

    // 0) fp16 conversions
    cvt_all<<<CVT_TOT / 1024, 256>>>(x, wqkv, wout, x16, wq16, wo16);

    // 1) QKV projection (fp16) -> fp16 q,k,v
    gemm_f16<2><<<dim3(3072 / 128, ROWS / 128), 128, GSMEM>>>(
        x16, wq16, nullptr, nullptr, qkv16, ROWS, 3072, EMB);

    // 2) causal flash attention (fp16, paired q-tiles) -> fp16
    attn_mma<<<dim3(8, NH, 2), 256, ASMEM>>>(qkv16, att16);

    // 3) out projection + bias (fp16) -> fp32
    gemm_f16<0><<<dim3(EMB / 128, ROWS / 128), 128, GSMEM>>>(
        att16, wo16, bout, out, nullptr, ROWS, EMB, EMB);
}